// round 5
// baseline (speedup 1.0000x reference)
#include <cuda_runtime.h>
#include <cstdint>

// Fixed problem shapes
static constexpr int B  = 8;
static constexpr int T  = 2048;
static constexpr int D  = 512;
static constexpr int K  = 3;
static constexpr int F  = 512;
static constexpr int BT = B * T;   // 16384 rows
static constexpr int F4 = F / 4;   // 128 float4 per row

static constexpr int TT     = 16;                 // t-rows per block
static constexpr int ITERS  = (TT * F4) / 256;    // 8 chunks of 256 float4-triples
static constexpr int STAGES = 3;                  // cp.async pipeline depth

__device__ __forceinline__ void cp_async16(uint32_t smem_addr, const void* gptr) {
    asm volatile("cp.async.cg.shared.global [%0], [%1], 16;"
                 :: "r"(smem_addr), "l"(gptr) : "memory");
}
__device__ __forceinline__ void cp_commit() {
    asm volatile("cp.async.commit_group;" ::: "memory");
}
template <int N>
__device__ __forceinline__ void cp_wait() {
    asm volatile("cp.async.wait_group %0;" :: "n"(N) : "memory");
}

__global__ void __launch_bounds__(256, 6) fused_dynconv_kernel(
    const float* __restrict__ x,
    const float* __restrict__ ker,
    float* __restrict__ out)
{
    // Staging: STAGES × 3 loads × 256 threads × float4 = 36 KB
    __shared__ float4 sm4[STAGES * 3 * 256];
    __shared__ float  s_s[TT + 2];

    const int tid  = threadIdx.x;
    const int bt0  = blockIdx.x * TT;
    const int t0   = bt0 & (T - 1);
    const int warp = tid >> 5;
    const int lane = tid & 31;

    const float4* __restrict__ kb =
        reinterpret_cast<const float4*>(ker + (size_t)bt0 * (K * F));
    float4* __restrict__ ob =
        reinterpret_cast<float4*>(out + (size_t)bt0 * F);

    // Helper lambda-free stage fill: iteration `it` into stage slot `st`
    // Thread tid handles output float4 idx = it*256+tid  -> row r, lane f4.
    auto fill_addr = [&](int it, int st) {
        const int idx = it * 256 + tid;
        const int r   = idx >> 7;             // F4 = 128
        const int f4  = idx & (F4 - 1);
        const float4* kr = kb + (size_t)r * (K * F4);
        uint32_t sb = (uint32_t)__cvta_generic_to_shared(&sm4[st * 768 + tid]);
        cp_async16(sb,               kr + f4);
        cp_async16(sb + 256  * 16,   kr + f4 + F4);
        cp_async16(sb + 512  * 16,   kr + f4 + 2 * F4);
        cp_commit();
    };

    // ---- Prologue: start filling stages for iterations 0 and 1 ----
    fill_addr(0, 0);
    fill_addr(1, 1);

    // ---- Phase 1: row sums for rows bt0-1 .. bt0+TT (18 rows, 8 warps) ----
    for (int r = warp; r < TT + 2; r += 8) {
        const int tg = t0 - 1 + r;
        float acc = 0.0f;
        if (tg >= 0 && tg < T) {
            const float4* __restrict__ xr =
                reinterpret_cast<const float4*>(x + (size_t)(bt0 - 1 + r) * D);
            float4 v0 = xr[lane];
            float4 v1 = xr[lane + 32];
            float4 v2 = xr[lane + 64];
            float4 v3 = xr[lane + 96];
            acc = ((v0.x + v0.y) + (v0.z + v0.w))
                + ((v1.x + v1.y) + (v1.z + v1.w))
                + ((v2.x + v2.y) + (v2.z + v2.w))
                + ((v3.x + v3.y) + (v3.z + v3.w));
#pragma unroll
            for (int o = 16; o > 0; o >>= 1)
                acc += __shfl_xor_sync(0xffffffffu, acc, o);
        }
        if (lane == 0)
            s_s[r] = acc;
    }
    __syncthreads();   // publish s_s (cp.async traffic unaffected)

    // ---- Phase 2: pipelined combine ----
#pragma unroll
    for (int it = 0; it < ITERS; ++it) {
        // Wait until stage `it` has landed. Pending groups allowed:
        // committed so far = min(ITERS, it+2); need group `it` complete.
        if (it < ITERS - 1) cp_wait<1>(); else cp_wait<0>();

        const int st = it % STAGES;
        float4 a = sm4[st * 768 + tid];
        float4 b = sm4[st * 768 + 256 + tid];
        float4 c = sm4[st * 768 + 512 + tid];

        // Kick off stage it+2 immediately after consuming slot becomes known-free?
        // Slot (it+2)%STAGES == (it-1)%STAGES: consumed at iteration it-1 by THIS
        // thread (thread-private readback), safe to overwrite now.
        if (it + 2 < ITERS)
            fill_addr(it + 2, (it + 2) % STAGES);

        const int idx = it * 256 + tid;
        const int r   = idx >> 7;
        const float sp = s_s[r];
        const float sc = s_s[r + 1];
        const float sn = s_s[r + 2];

        float4 o;
        o.x = fmaf(sp, a.x, fmaf(sc, b.x, sn * c.x));
        o.y = fmaf(sp, a.y, fmaf(sc, b.y, sn * c.y));
        o.z = fmaf(sp, a.z, fmaf(sc, b.z, sn * c.z));
        o.w = fmaf(sp, a.w, fmaf(sc, b.w, sn * c.w));
        __stcs(ob + idx, o);
    }
}

extern "C" void kernel_launch(void* const* d_in, const int* in_sizes, int n_in,
                              void* d_out, int out_size) {
    const float* x   = (const float*)d_in[0];   // [B, T, D]
    const float* ker = (const float*)d_in[1];   // [B, T, K, F]
    float* out = (float*)d_out;                 // [B, T, F]
    (void)in_sizes; (void)n_in; (void)out_size;

    fused_dynconv_kernel<<<BT / TT, 256>>>(x, ker, out);
}

// round 7
// speedup vs baseline: 1.3412x; 1.3412x over previous
#include <cuda_runtime.h>
#include <cstdint>

// Fixed problem shapes
static constexpr int B  = 8;
static constexpr int T  = 2048;
static constexpr int D  = 512;
static constexpr int K  = 3;
static constexpr int F  = 512;
static constexpr int BT = B * T;   // 16384 rows
static constexpr int F4 = F / 4;   // 128 float4 per row

static constexpr int TT    = 16;                // t-rows per block
static constexpr int ITERS = (TT * F4) / 256;   // 8

// L2 evict_last access policy (created once per thread; cheap U-pipe op).
__device__ __forceinline__ uint64_t make_evict_last_policy() {
    uint64_t pol;
    asm volatile("createpolicy.fractional.L2::evict_last.b64 %0, 1.0;" : "=l"(pol));
    return pol;
}

// Persist-load: x is 32 MB, re-read every replay -> keep resident in L2.
__device__ __forceinline__ float4 ldg_el(const float4* p, uint64_t pol) {
    float4 v;
    asm volatile("ld.global.L2::cache_hint.v4.f32 {%0,%1,%2,%3}, [%4], %5;"
                 : "=f"(v.x), "=f"(v.y), "=f"(v.z), "=f"(v.w)
                 : "l"(p), "l"(pol));
    return v;
}

// Persist-store: out is 32 MB, overwritten every replay -> keep dirty lines in
// L2 so they are re-dirtied in place instead of being written back to DRAM.
__device__ __forceinline__ void stg_el(float4* p, float4 v, uint64_t pol) {
    asm volatile("st.global.L2::cache_hint.v4.f32 [%0], {%1,%2,%3,%4}, %5;"
                 :: "l"(p), "f"(v.x), "f"(v.y), "f"(v.z), "f"(v.w), "l"(pol)
                 : "memory");
}

__global__ void __launch_bounds__(256, 4) fused_dynconv_kernel(
    const float* __restrict__ x,
    const float* __restrict__ ker,
    float* __restrict__ out)
{
    __shared__ float s_s[TT + 2];

    const int tid  = threadIdx.x;
    const int bt0  = blockIdx.x * TT;
    const int t0   = bt0 & (T - 1);           // T = 2048, power of 2
    const int warp = tid >> 5;
    const int lane = tid & 31;

    const uint64_t pol = make_evict_last_policy();

    const float4* __restrict__ kb =
        reinterpret_cast<const float4*>(ker + (size_t)bt0 * (K * F));
    float4* __restrict__ ob =
        reinterpret_cast<float4*>(out + (size_t)bt0 * F);

    // ---- Prefetch kernels-loads for iterations 0 and 1 BEFORE the barrier.
    // Independent of the row sums; keeps the memory pipe full during phase 1.
    const int idx0 = tid;
    const int idx1 = 256 + tid;
    const int r0 = idx0 >> 7, f40 = idx0 & (F4 - 1);
    const int r1 = idx1 >> 7, f41 = idx1 & (F4 - 1);
    const float4* kr0 = kb + (size_t)r0 * (K * F4);
    const float4* kr1 = kb + (size_t)r1 * (K * F4);
    float4 pa0 = __ldcs(kr0 + f40);
    float4 pb0 = __ldcs(kr0 + f40 + F4);
    float4 pc0 = __ldcs(kr0 + f40 + 2 * F4);
    float4 pa1 = __ldcs(kr1 + f41);
    float4 pb1 = __ldcs(kr1 + f41 + F4);
    float4 pc1 = __ldcs(kr1 + f41 + 2 * F4);

    // ---- Phase 1: row sums for rows bt0-1 .. bt0+TT (18 rows, 8 warps) ----
    for (int r = warp; r < TT + 2; r += 8) {
        const int tg = t0 - 1 + r;
        float acc = 0.0f;
        if (tg >= 0 && tg < T) {
            const float4* __restrict__ xr =
                reinterpret_cast<const float4*>(x + (size_t)(bt0 - 1 + r) * D);
            float4 v0 = ldg_el(xr + lane,      pol);
            float4 v1 = ldg_el(xr + lane + 32, pol);
            float4 v2 = ldg_el(xr + lane + 64, pol);
            float4 v3 = ldg_el(xr + lane + 96, pol);
            acc = ((v0.x + v0.y) + (v0.z + v0.w))
                + ((v1.x + v1.y) + (v1.z + v1.w))
                + ((v2.x + v2.y) + (v2.z + v2.w))
                + ((v3.x + v3.y) + (v3.z + v3.w));
#pragma unroll
            for (int o = 16; o > 0; o >>= 1)
                acc += __shfl_xor_sync(0xffffffffu, acc, o);
        }
        if (lane == 0)
            s_s[r] = acc;
    }
    __syncthreads();

    // ---- Phase 2: depth-2 software-pipelined combine ----
#pragma unroll
    for (int it = 0; it < ITERS; ++it) {
        float4 na, nb, nc;
        if (it + 2 < ITERS) {
            const int idxn = (it + 2) * 256 + tid;
            const int rn = idxn >> 7, f4n = idxn & (F4 - 1);
            const float4* krn = kb + (size_t)rn * (K * F4);
            na = __ldcs(krn + f4n);
            nb = __ldcs(krn + f4n + F4);
            nc = __ldcs(krn + f4n + 2 * F4);
        }

        const int idx = it * 256 + tid;
        const int r   = idx >> 7;
        const float sp = s_s[r];
        const float sc = s_s[r + 1];
        const float sn = s_s[r + 2];

        float4 o;
        o.x = fmaf(sp, pa0.x, fmaf(sc, pb0.x, sn * pc0.x));
        o.y = fmaf(sp, pa0.y, fmaf(sc, pb0.y, sn * pc0.y));
        o.z = fmaf(sp, pa0.z, fmaf(sc, pb0.z, sn * pc0.z));
        o.w = fmaf(sp, pa0.w, fmaf(sc, pb0.w, sn * pc0.w));
        stg_el(ob + idx, o, pol);

        pa0 = pa1; pb0 = pb1; pc0 = pc1;
        pa1 = na;  pb1 = nb;  pc1 = nc;
    }
}

extern "C" void kernel_launch(void* const* d_in, const int* in_sizes, int n_in,
                              void* d_out, int out_size) {
    const float* x   = (const float*)d_in[0];   // [B, T, D]
    const float* ker = (const float*)d_in[1];   // [B, T, K, F]
    float* out = (float*)d_out;                 // [B, T, F]
    (void)in_sizes; (void)n_in; (void)out_size;

    fused_dynconv_kernel<<<BT / TT, 256>>>(x, ker, out);
}

// round 9
// speedup vs baseline: 1.4194x; 1.0583x over previous
#include <cuda_runtime.h>
#include <cstdint>

// Fixed problem shapes
static constexpr int B  = 8;
static constexpr int T  = 2048;
static constexpr int D  = 512;
static constexpr int K  = 3;
static constexpr int F  = 512;
static constexpr int BT = B * T;   // 16384 rows
static constexpr int F4 = F / 4;   // 128 float4 per row

static constexpr int TT    = 16;                // t-rows per block
static constexpr int ITERS = (TT * F4) / 256;   // 8

__global__ void __launch_bounds__(256, 4) fused_dynconv_kernel(
    const float* __restrict__ x,
    const float* __restrict__ ker,
    float* __restrict__ out)
{
    __shared__ float s_s[TT + 2];

    const int tid  = threadIdx.x;
    const int bt0  = blockIdx.x * TT;
    const int t0   = bt0 & (T - 1);           // T = 2048, power of 2
    const int warp = tid >> 5;
    const int lane = tid & 31;

    const float4* __restrict__ kb =
        reinterpret_cast<const float4*>(ker + (size_t)bt0 * (K * F));
    float4* __restrict__ ob =
        reinterpret_cast<float4*>(out + (size_t)bt0 * F);

    // ---- Prefetch kernels-loads for iterations 0 and 1 BEFORE the barrier.
    // Independent of the row sums; keeps the memory pipe full during phase 1.
    const int idx0 = tid;
    const int idx1 = 256 + tid;
    const int r0 = idx0 >> 7, f40 = idx0 & (F4 - 1);
    const int r1 = idx1 >> 7, f41 = idx1 & (F4 - 1);
    const float4* kr0 = kb + (size_t)r0 * (K * F4);
    const float4* kr1 = kb + (size_t)r1 * (K * F4);
    float4 pa0 = __ldcs(kr0 + f40);
    float4 pb0 = __ldcs(kr0 + f40 + F4);
    float4 pc0 = __ldcs(kr0 + f40 + 2 * F4);
    float4 pa1 = __ldcs(kr1 + f41);
    float4 pb1 = __ldcs(kr1 + f41 + F4);
    float4 pc1 = __ldcs(kr1 + f41 + 2 * F4);

    // ---- Phase 1: row sums for rows bt0-1 .. bt0+TT (18 rows, 8 warps) ----
    // x loads use DEFAULT policy: x re-read every replay, want it L2-resident.
    for (int r = warp; r < TT + 2; r += 8) {
        const int tg = t0 - 1 + r;
        float acc = 0.0f;
        if (tg >= 0 && tg < T) {
            const float4* __restrict__ xr =
                reinterpret_cast<const float4*>(x + (size_t)(bt0 - 1 + r) * D);
            float4 v0 = xr[lane];
            float4 v1 = xr[lane + 32];
            float4 v2 = xr[lane + 64];
            float4 v3 = xr[lane + 96];
            acc = ((v0.x + v0.y) + (v0.z + v0.w))
                + ((v1.x + v1.y) + (v1.z + v1.w))
                + ((v2.x + v2.y) + (v2.z + v2.w))
                + ((v3.x + v3.y) + (v3.z + v3.w));
#pragma unroll
            for (int o = 16; o > 0; o >>= 1)
                acc += __shfl_xor_sync(0xffffffffu, acc, o);
        }
        if (lane == 0)
            s_s[r] = acc;
    }
    __syncthreads();

    // ---- Phase 2: depth-2 software-pipelined combine ----
#pragma unroll
    for (int it = 0; it < ITERS; ++it) {
        float4 na, nb, nc;
        if (it + 2 < ITERS) {
            const int idxn = (it + 2) * 256 + tid;
            const int rn = idxn >> 7, f4n = idxn & (F4 - 1);
            const float4* krn = kb + (size_t)rn * (K * F4);
            na = __ldcs(krn + f4n);
            nb = __ldcs(krn + f4n + F4);
            nc = __ldcs(krn + f4n + 2 * F4);
        }

        const int idx = it * 256 + tid;
        const int r   = idx >> 7;
        const float sp = s_s[r];
        const float sc = s_s[r + 1];
        const float sn = s_s[r + 2];

        float4 o;
        o.x = fmaf(sp, pa0.x, fmaf(sc, pb0.x, sn * pc0.x));
        o.y = fmaf(sp, pa0.y, fmaf(sc, pb0.y, sn * pc0.y));
        o.z = fmaf(sp, pa0.z, fmaf(sc, pb0.z, sn * pc0.z));
        o.w = fmaf(sp, pa0.w, fmaf(sc, pb0.w, sn * pc0.w));
        // DEFAULT-policy store: keep out's dirty lines at normal LRU priority so
        // they survive in L2 across graph replays (re-dirtied in place, no
        // DRAM write-back). __stcs here would mark them evict-first and force
        // a 32 MB/replay write-back stream.
        ob[idx] = o;

        pa0 = pa1; pb0 = pb1; pc0 = pc1;
        pa1 = na;  pb1 = nb;  pc1 = nc;
    }
}

extern "C" void kernel_launch(void* const* d_in, const int* in_sizes, int n_in,
                              void* d_out, int out_size) {
    const float* x   = (const float*)d_in[0];   // [B, T, D]
    const float* ker = (const float*)d_in[1];   // [B, T, K, F]
    float* out = (float*)d_out;                 // [B, T, F]
    (void)in_sizes; (void)n_in; (void)out_size;

    fused_dynconv_kernel<<<BT / TT, 256>>>(x, ker, out);
}